// round 2
// baseline (speedup 1.0000x reference)
#include <cuda_runtime.h>
#include <math.h>

// Problem constants
#define Bsz   4
#define Csz   16
#define Tsz   32
#define Hsz   128
#define Wsz   128
#define Klow  4
#define TAU   0.1
#define EPS2  1e-12f          // (1e-6)^2

#define HW        (Hsz * Wsz)          // 16384
#define HW4       (HW / 4)             // 4096
#define NLOC      (Bsz * Csz * HW)     // 1,048,576 spatial locations
#define NTHREADS  (NLOC / 4)           // 262,144 threads (4 loc / thread via 16B loads)
#define BLOCK     256
#define NBLOCKS   (NTHREADS / BLOCK)   // 1024

#define N_MAIN  ((double)Bsz * Csz * Tsz * HW)          // 33,554,432
#define N_TEMP  ((double)Bsz * Csz * (Tsz - 1) * HW)    // 32,505,856

typedef unsigned long long u64;

// ---- f32x2 packed helpers (sm_103a; ptxas never emits these from C++) ----
__device__ __forceinline__ u64 fma2(u64 a, u64 b, u64 c) {
    u64 r; asm("fma.rn.f32x2 %0, %1, %2, %3;" : "=l"(r) : "l"(a), "l"(b), "l"(c));
    return r;
}
__device__ __forceinline__ u64 pack2(float lo, float hi) {
    u64 r; asm("mov.b64 %0, {%1, %2};" : "=l"(r) : "f"(lo), "f"(hi));
    return r;
}
__device__ __forceinline__ void unpack2(u64 v, float& lo, float& hi) {
    asm("mov.b64 {%0, %1}, %2;" : "=f"(lo), "=f"(hi) : "l"(v));
}

__device__ float g_partials[2 * NBLOCKS];
__device__ unsigned int g_count = 0;   // last block resets to 0 -> graph-replay safe

__global__ void __launch_bounds__(BLOCK)
loss_fused(const ulonglong2* __restrict__ X, const ulonglong2* __restrict__ Y,
           float* __restrict__ out)
{
    __shared__ float sD[Klow][Tsz];    // orthonormal DCT rows 0..3
    __shared__ u64   sW[Klow][Tsz];    // packed {w,w} broadcast weights
    __shared__ float sG[Klow * Klow];  // G = E E^T, E[n,s] = D[n,s+1]-D[n,s]
    __shared__ float red[2][BLOCK];
    __shared__ bool  is_last;

    const int tid = threadIdx.x;

    // Build D (4x32)
    if (tid < Klow * Tsz) {
        int n = tid >> 5;
        int t = tid & 31;
        float v = sqrtf(2.0f / (float)Tsz) *
                  cosf((float)M_PI * (2.0f * t + 1.0f) * (float)n / (2.0f * (float)Tsz));
        if (n == 0) v *= 0.7071067811865476f;
        sD[n][t] = v;
        sW[n][t] = pack2(v, v);
    }
    __syncthreads();
    if (tid < Klow * Klow) {
        int n = tid >> 2;
        int m = tid & 3;
        float g = 0.0f;
        #pragma unroll
        for (int s = 0; s < Tsz - 1; s++) {
            float en = sD[n][s + 1] - sD[n][s];
            float em = sD[m][s + 1] - sD[m][s];
            g += en * em;
        }
        sG[tid] = g;
    }
    __syncthreads();

    // Each thread walks one 16B column (4 spatial locations) through T
    const unsigned i   = blockIdx.x * BLOCK + tid;
    const unsigned hw4 = i & (HW4 - 1);
    const unsigned bc  = i >> 12;               // i / HW4
    const size_t base  = (size_t)bc * (Tsz * HW4) + hw4;

    const u64 NEG1 = pack2(-1.0f, -1.0f);
    const u64 EPSP = pack2(EPS2, EPS2);

    float charb = 0.0f;
    u64 c01[Klow], c23[Klow];
    #pragma unroll
    for (int n = 0; n < Klow; n++) { c01[n] = 0ull; c23[n] = 0ull; }

    #pragma unroll 8
    for (int t = 0; t < Tsz; t++) {
        ulonglong2 a = X[base + (size_t)t * HW4];
        ulonglong2 b = Y[base + (size_t)t * HW4];
        u64 d01 = fma2(b.x, NEG1, a.x);   // a - b
        u64 d23 = fma2(b.y, NEG1, a.y);

        #pragma unroll
        for (int n = 0; n < Klow; n++) {
            u64 w = sW[n][t];
            c01[n] = fma2(d01, w, c01[n]);
            c23[n] = fma2(d23, w, c23[n]);
        }

        u64 s01 = fma2(d01, d01, EPSP);
        u64 s23 = fma2(d23, d23, EPSP);
        float s0, s1, s2, s3;
        unpack2(s01, s0, s1);
        unpack2(s23, s2, s3);
        // sqrt(s) = s * rsqrt(s)  (MUFU.RSQ + FFMA, s >= EPS2 > 0)
        charb = fmaf(s0, __frsqrt_rn(s0), charb);
        charb = fmaf(s1, __frsqrt_rn(s1), charb);
        charb = fmaf(s2, __frsqrt_rn(s2), charb);
        charb = fmaf(s3, __frsqrt_rn(s3), charb);
    }

    // temp = sum over the 4 lanes of c^T G c
    float temp = 0.0f;
    {
        float cl[4][Klow];
        #pragma unroll
        for (int n = 0; n < Klow; n++) {
            unpack2(c01[n], cl[0][n], cl[1][n]);
            unpack2(c23[n], cl[2][n], cl[3][n]);
        }
        #pragma unroll
        for (int l = 0; l < 4; l++) {
            #pragma unroll
            for (int n = 0; n < Klow; n++) {
                float acc = 0.0f;
                #pragma unroll
                for (int m = 0; m < Klow; m++)
                    acc = fmaf(cl[l][m], sG[n * Klow + m], acc);
                temp = fmaf(cl[l][n], acc, temp);
            }
        }
    }

    // Deterministic block reduction
    red[0][tid] = charb;
    red[1][tid] = temp;
    __syncthreads();
    for (int s = BLOCK / 2; s > 0; s >>= 1) {
        if (tid < s) {
            red[0][tid] += red[0][tid + s];
            red[1][tid] += red[1][tid + s];
        }
        __syncthreads();
    }

    if (tid == 0) {
        g_partials[blockIdx.x]           = red[0][0];
        g_partials[NBLOCKS + blockIdx.x] = red[1][0];
        __threadfence();
        unsigned int ticket = atomicAdd(&g_count, 1u);
        is_last = (ticket == NBLOCKS - 1);
    }
    __syncthreads();

    // Last block: deterministic final reduction in double
    if (is_last) {
        __shared__ double r0[BLOCK];
        __shared__ double r1[BLOCK];
        double s0 = 0.0, s1 = 0.0;
        #pragma unroll 4
        for (int k = tid; k < NBLOCKS; k += BLOCK) {
            s0 += (double)__ldcg(&g_partials[k]);
            s1 += (double)__ldcg(&g_partials[NBLOCKS + k]);
        }
        r0[tid] = s0;
        r1[tid] = s1;
        __syncthreads();
        for (int s = BLOCK / 2; s > 0; s >>= 1) {
            if (tid < s) {
                r0[tid] += r0[tid + s];
                r1[tid] += r1[tid + s];
            }
            __syncthreads();
        }
        if (tid == 0) {
            double L_main = r0[0] / N_MAIN;
            double L_temp = r1[0] / N_TEMP;
            double total  = L_main + TAU * L_temp;
            out[0] = (float)total;
            out[1] = (float)L_main;
            out[2] = (float)L_temp;
            g_count = 0;   // reset for next (graph-replayed) launch
        }
    }
}

extern "C" void kernel_launch(void* const* d_in, const int* in_sizes, int n_in,
                              void* d_out, int out_size)
{
    const ulonglong2* X = (const ulonglong2*)d_in[0];
    const ulonglong2* Y = (const ulonglong2*)d_in[1];
    float* out = (float*)d_out;

    loss_fused<<<NBLOCKS, BLOCK>>>(X, Y, out);
}

// round 4
// speedup vs baseline: 1.0071x; 1.0071x over previous
#include <cuda_runtime.h>
#include <math.h>

// Problem constants
#define Bsz   4
#define Csz   16
#define Tsz   32
#define Hsz   128
#define Wsz   128
#define Klow  4
#define TAU   0.1
#define EPS2  1e-12f          // (1e-6)^2

#define HW        (Hsz * Wsz)          // 16384
#define HW4       (HW / 4)             // 4096
#define NLOC      (Bsz * Csz * HW)     // 1,048,576 spatial locations
#define NTHREADS  (NLOC / 4)           // 262,144 threads (4 loc / thread, float4)
#define BLOCK     256
#define NBLOCKS   (NTHREADS / BLOCK)   // 1024

#define N_MAIN  ((double)Bsz * Csz * Tsz * HW)          // 33,554,432
#define N_TEMP  ((double)Bsz * Csz * (Tsz - 1) * HW)    // 32,505,856

__device__ float g_partials[2 * NBLOCKS];
__device__ unsigned int g_count = 0;   // last block resets -> graph-replay safe

__global__ void __launch_bounds__(BLOCK)
loss_fused(const float4* __restrict__ X, const float4* __restrict__ Y,
           float* __restrict__ out)
{
    __shared__ float  sD[Klow][Tsz];    // orthonormal DCT rows (for building G)
    __shared__ float4 sWT[Tsz];         // per-t packed weights {w0,w1,w2,w3}
    __shared__ float  sG[Klow * Klow];  // G = E E^T
    __shared__ float  red[2][BLOCK];
    __shared__ bool   is_last;

    const int tid = threadIdx.x;

    // Build D (4x32): 32 threads, 4 rows each; pack into float4 per t
    if (tid < Tsz) {
        const float s  = sqrtf(2.0f / (float)Tsz);
        const float ph = (float)M_PI * (2.0f * tid + 1.0f) / (2.0f * (float)Tsz);
        float w0 = s * 0.7071067811865476f;
        float w1 = s * cosf(ph);
        float w2 = s * cosf(2.0f * ph);
        float w3 = s * cosf(3.0f * ph);
        sD[0][tid] = w0; sD[1][tid] = w1; sD[2][tid] = w2; sD[3][tid] = w3;
        sWT[tid] = make_float4(w0, w1, w2, w3);
    }
    __syncthreads();
    if (tid < Klow * Klow) {
        int n = tid >> 2, m = tid & 3;
        float g = 0.0f;
        #pragma unroll
        for (int s = 0; s < Tsz - 1; s++)
            g += (sD[n][s + 1] - sD[n][s]) * (sD[m][s + 1] - sD[m][s]);
        sG[tid] = g;
    }
    __syncthreads();

    // Each thread walks one 16B column (4 spatial locations) through T.
    const unsigned i   = blockIdx.x * BLOCK + tid;
    const unsigned hw4 = i & (HW4 - 1);
    const unsigned bc  = i >> 12;               // i / HW4
    const size_t base  = (size_t)bc * (Tsz * HW4) + hw4;
    const float4* __restrict__ px = X + base;
    const float4* __restrict__ py = Y + base;

    float ch0 = 0.f, ch1 = 0.f, ch2 = 0.f, ch3 = 0.f;
    float c[Klow][4];                 // [dct row][lane]
    #pragma unroll
    for (int n = 0; n < Klow; n++)
        #pragma unroll
        for (int l = 0; l < 4; l++) c[n][l] = 0.0f;

    // Manual 4-timestep staging: 8 independent LDG.128 issued before any use.
    #pragma unroll
    for (int tt = 0; tt < Tsz; tt += 4) {
        float4 a[4], b[4];
        #pragma unroll
        for (int j = 0; j < 4; j++) {
            a[j] = __ldcs(&px[(tt + j) * HW4]);
            b[j] = __ldcs(&py[(tt + j) * HW4]);
        }
        #pragma unroll
        for (int j = 0; j < 4; j++) {
            float d0 = a[j].x - b[j].x;
            float d1 = a[j].y - b[j].y;
            float d2 = a[j].z - b[j].z;
            float d3 = a[j].w - b[j].w;

            float s0 = fmaf(d0, d0, EPS2);
            float s1 = fmaf(d1, d1, EPS2);
            float s2 = fmaf(d2, d2, EPS2);
            float s3 = fmaf(d3, d3, EPS2);
            ch0 = fmaf(s0, __frsqrt_rn(s0), ch0);   // sqrt(s) = s*rsqrt(s)
            ch1 = fmaf(s1, __frsqrt_rn(s1), ch1);
            ch2 = fmaf(s2, __frsqrt_rn(s2), ch2);
            ch3 = fmaf(s3, __frsqrt_rn(s3), ch3);

            const float4 w = sWT[tt + j];           // one broadcast LDS.128
            c[0][0] = fmaf(d0, w.x, c[0][0]);
            c[0][1] = fmaf(d1, w.x, c[0][1]);
            c[0][2] = fmaf(d2, w.x, c[0][2]);
            c[0][3] = fmaf(d3, w.x, c[0][3]);
            c[1][0] = fmaf(d0, w.y, c[1][0]);
            c[1][1] = fmaf(d1, w.y, c[1][1]);
            c[1][2] = fmaf(d2, w.y, c[1][2]);
            c[1][3] = fmaf(d3, w.y, c[1][3]);
            c[2][0] = fmaf(d0, w.z, c[2][0]);
            c[2][1] = fmaf(d1, w.z, c[2][1]);
            c[2][2] = fmaf(d2, w.z, c[2][2]);
            c[2][3] = fmaf(d3, w.z, c[2][3]);
            c[3][0] = fmaf(d0, w.w, c[3][0]);
            c[3][1] = fmaf(d1, w.w, c[3][1]);
            c[3][2] = fmaf(d2, w.w, c[3][2]);
            c[3][3] = fmaf(d3, w.w, c[3][3]);
        }
    }
    float charb = (ch0 + ch1) + (ch2 + ch3);

    // temp = sum over 4 lanes of c^T G c
    float temp = 0.0f;
    #pragma unroll
    for (int l = 0; l < 4; l++) {
        #pragma unroll
        for (int n = 0; n < Klow; n++) {
            float acc = 0.0f;
            #pragma unroll
            for (int m = 0; m < Klow; m++)
                acc = fmaf(c[m][l], sG[n * Klow + m], acc);
            temp = fmaf(c[n][l], acc, temp);
        }
    }

    // Deterministic block reduction
    red[0][tid] = charb;
    red[1][tid] = temp;
    __syncthreads();
    for (int s = BLOCK / 2; s > 0; s >>= 1) {
        if (tid < s) {
            red[0][tid] += red[0][tid + s];
            red[1][tid] += red[1][tid + s];
        }
        __syncthreads();
    }

    if (tid == 0) {
        g_partials[blockIdx.x]           = red[0][0];
        g_partials[NBLOCKS + blockIdx.x] = red[1][0];
        __threadfence();
        unsigned int ticket = atomicAdd(&g_count, 1u);
        is_last = (ticket == NBLOCKS - 1);
    }
    __syncthreads();

    // Last block: deterministic final reduction in double
    if (is_last) {
        __shared__ double r0[BLOCK];
        __shared__ double r1[BLOCK];
        double s0 = 0.0, s1 = 0.0;
        #pragma unroll 4
        for (int k = tid; k < NBLOCKS; k += BLOCK) {
            s0 += (double)__ldcg(&g_partials[k]);
            s1 += (double)__ldcg(&g_partials[NBLOCKS + k]);
        }
        r0[tid] = s0;
        r1[tid] = s1;
        __syncthreads();
        for (int s = BLOCK / 2; s > 0; s >>= 1) {
            if (tid < s) {
                r0[tid] += r0[tid + s];
                r1[tid] += r1[tid + s];
            }
            __syncthreads();
        }
        if (tid == 0) {
            double L_main = r0[0] / N_MAIN;
            double L_temp = r1[0] / N_TEMP;
            double total  = L_main + TAU * L_temp;
            out[0] = (float)total;
            out[1] = (float)L_main;
            out[2] = (float)L_temp;
            g_count = 0;   // reset for next graph replay
        }
    }
}

extern "C" void kernel_launch(void* const* d_in, const int* in_sizes, int n_in,
                              void* d_out, int out_size)
{
    const float4* X = (const float4*)d_in[0];
    const float4* Y = (const float4*)d_in[1];
    float* out = (float*)d_out;

    loss_fused<<<NBLOCKS, BLOCK>>>(X, Y, out);
}

// round 5
// speedup vs baseline: 1.3285x; 1.3192x over previous
#include <cuda_runtime.h>
#include <math.h>

// Problem constants
#define Bsz   4
#define Csz   16
#define Tsz   32
#define Hsz   128
#define Wsz   128
#define Klow  4
#define TAU   0.1
#define EPS2  1e-12f          // (1e-6)^2

#define HW        (Hsz * Wsz)          // 16384
#define HW4       (HW / 4)             // 4096
#define NLOC      (Bsz * Csz * HW)     // 1,048,576 spatial locations
#define NTHREADS  (NLOC / 4)           // 262,144 threads (4 loc / thread, float4)
#define BLOCK     256
#define NBLOCKS   (NTHREADS / BLOCK)   // 1024

#define N_MAIN  ((double)Bsz * Csz * Tsz * HW)          // 33,554,432
#define N_TEMP  ((double)Bsz * Csz * (Tsz - 1) * HW)    // 32,505,856

__device__ float g_partials[2 * NBLOCKS];
__device__ unsigned int g_count = 0;   // last block resets -> graph-replay safe

// Single-MUFU sqrt (no -use_fast_math in harness, so sqrtf/__frsqrt_rn emit
// a ~15-instruction correctly-rounded emulation sequence; this is 1 instr).
__device__ __forceinline__ float sqrt_approx(float x) {
    float r;
    asm("sqrt.approx.f32 %0, %1;" : "=f"(r) : "f"(x));
    return r;
}

__global__ void __launch_bounds__(BLOCK)
loss_fused(const float4* __restrict__ X, const float4* __restrict__ Y,
           float* __restrict__ out)
{
    __shared__ float  sD[Klow][Tsz];    // orthonormal DCT rows (for building G)
    __shared__ float4 sWT[Tsz];         // per-t packed weights {w0,w1,w2,w3}
    __shared__ float  sG[Klow * Klow];  // G = E E^T
    __shared__ float  red[2][BLOCK];
    __shared__ bool   is_last;

    const int tid = threadIdx.x;

    // Build D (4x32): one thread per t; pack into float4 per t.
    if (tid < Tsz) {
        const float s  = sqrtf(2.0f / (float)Tsz);   // setup only — cost irrelevant
        const float ph = (float)M_PI * (2.0f * tid + 1.0f) / (2.0f * (float)Tsz);
        float w0 = s * 0.7071067811865476f;
        float w1 = s * cosf(ph);
        float w2 = s * cosf(2.0f * ph);
        float w3 = s * cosf(3.0f * ph);
        sD[0][tid] = w0; sD[1][tid] = w1; sD[2][tid] = w2; sD[3][tid] = w3;
        sWT[tid] = make_float4(w0, w1, w2, w3);
    }
    __syncthreads();
    if (tid < Klow * Klow) {
        int n = tid >> 2, m = tid & 3;
        float g = 0.0f;
        #pragma unroll
        for (int s = 0; s < Tsz - 1; s++)
            g += (sD[n][s + 1] - sD[n][s]) * (sD[m][s + 1] - sD[m][s]);
        sG[tid] = g;
    }
    __syncthreads();

    // Each thread walks one 16B column (4 spatial locations) through T.
    const unsigned i   = blockIdx.x * BLOCK + tid;
    const unsigned hw4 = i & (HW4 - 1);
    const unsigned bc  = i >> 12;               // i / HW4
    const size_t base  = (size_t)bc * (Tsz * HW4) + hw4;
    const float4* __restrict__ px = X + base;
    const float4* __restrict__ py = Y + base;

    float ch0 = 0.f, ch1 = 0.f, ch2 = 0.f, ch3 = 0.f;
    float c[Klow][4];                 // [dct row][lane]
    #pragma unroll
    for (int n = 0; n < Klow; n++)
        #pragma unroll
        for (int l = 0; l < 4; l++) c[n][l] = 0.0f;

    // 4-timestep staging: 8 independent LDG.128 issued before any use.
    #pragma unroll
    for (int tt = 0; tt < Tsz; tt += 4) {
        float4 a[4], b[4];
        #pragma unroll
        for (int j = 0; j < 4; j++) {
            a[j] = __ldcs(&px[(tt + j) * HW4]);
            b[j] = __ldcs(&py[(tt + j) * HW4]);
        }
        #pragma unroll
        for (int j = 0; j < 4; j++) {
            float d0 = a[j].x - b[j].x;
            float d1 = a[j].y - b[j].y;
            float d2 = a[j].z - b[j].z;
            float d3 = a[j].w - b[j].w;

            // Charbonnier: MUFU.RSQ-class single-instruction sqrt
            ch0 += sqrt_approx(fmaf(d0, d0, EPS2));
            ch1 += sqrt_approx(fmaf(d1, d1, EPS2));
            ch2 += sqrt_approx(fmaf(d2, d2, EPS2));
            ch3 += sqrt_approx(fmaf(d3, d3, EPS2));

            const float4 w = sWT[tt + j];           // one broadcast LDS.128
            c[0][0] = fmaf(d0, w.x, c[0][0]);
            c[0][1] = fmaf(d1, w.x, c[0][1]);
            c[0][2] = fmaf(d2, w.x, c[0][2]);
            c[0][3] = fmaf(d3, w.x, c[0][3]);
            c[1][0] = fmaf(d0, w.y, c[1][0]);
            c[1][1] = fmaf(d1, w.y, c[1][1]);
            c[1][2] = fmaf(d2, w.y, c[1][2]);
            c[1][3] = fmaf(d3, w.y, c[1][3]);
            c[2][0] = fmaf(d0, w.z, c[2][0]);
            c[2][1] = fmaf(d1, w.z, c[2][1]);
            c[2][2] = fmaf(d2, w.z, c[2][2]);
            c[2][3] = fmaf(d3, w.z, c[2][3]);
            c[3][0] = fmaf(d0, w.w, c[3][0]);
            c[3][1] = fmaf(d1, w.w, c[3][1]);
            c[3][2] = fmaf(d2, w.w, c[3][2]);
            c[3][3] = fmaf(d3, w.w, c[3][3]);
        }
    }
    float charb = (ch0 + ch1) + (ch2 + ch3);

    // temp = sum over 4 lanes of c^T G c
    float temp = 0.0f;
    #pragma unroll
    for (int l = 0; l < 4; l++) {
        #pragma unroll
        for (int n = 0; n < Klow; n++) {
            float acc = 0.0f;
            #pragma unroll
            for (int m = 0; m < Klow; m++)
                acc = fmaf(c[m][l], sG[n * Klow + m], acc);
            temp = fmaf(c[n][l], acc, temp);
        }
    }

    // Deterministic block reduction
    red[0][tid] = charb;
    red[1][tid] = temp;
    __syncthreads();
    for (int s = BLOCK / 2; s > 0; s >>= 1) {
        if (tid < s) {
            red[0][tid] += red[0][tid + s];
            red[1][tid] += red[1][tid + s];
        }
        __syncthreads();
    }

    if (tid == 0) {
        g_partials[blockIdx.x]           = red[0][0];
        g_partials[NBLOCKS + blockIdx.x] = red[1][0];
        __threadfence();
        unsigned int ticket = atomicAdd(&g_count, 1u);
        is_last = (ticket == NBLOCKS - 1);
    }
    __syncthreads();

    // Last block: deterministic final reduction in double
    if (is_last) {
        __shared__ double r0[BLOCK];
        __shared__ double r1[BLOCK];
        double s0 = 0.0, s1 = 0.0;
        #pragma unroll 4
        for (int k = tid; k < NBLOCKS; k += BLOCK) {
            s0 += (double)__ldcg(&g_partials[k]);
            s1 += (double)__ldcg(&g_partials[NBLOCKS + k]);
        }
        r0[tid] = s0;
        r1[tid] = s1;
        __syncthreads();
        for (int s = BLOCK / 2; s > 0; s >>= 1) {
            if (tid < s) {
                r0[tid] += r0[tid + s];
                r1[tid] += r1[tid + s];
            }
            __syncthreads();
        }
        if (tid == 0) {
            double L_main = r0[0] / N_MAIN;
            double L_temp = r1[0] / N_TEMP;
            double total  = L_main + TAU * L_temp;
            out[0] = (float)total;
            out[1] = (float)L_main;
            out[2] = (float)L_temp;
            g_count = 0;   // reset for next graph replay
        }
    }
}

extern "C" void kernel_launch(void* const* d_in, const int* in_sizes, int n_in,
                              void* d_out, int out_size)
{
    const float4* X = (const float4*)d_in[0];
    const float4* Y = (const float4*)d_in[1];
    float* out = (float*)d_out;

    loss_fused<<<NBLOCKS, BLOCK>>>(X, Y, out);
}